// round 3
// baseline (speedup 1.0000x reference)
#include <cuda_runtime.h>
#include <math.h>
#include <stdint.h>

// ---------------- problem constants ----------------
#define NLVL   12
#define TBL    (1u << 19)
#define TMASK  (TBL - 1u)
#define EMBD   24
#define DOUT   257
#define TPB    128
#define TILE_P 128

#define PRIME_Y 2654435761u
#define PRIME_Z 805459861u

struct Params { int res[NLVL]; };

// ---------------- f32x2 packed helpers (sm_103a) ----------------
__device__ __forceinline__ unsigned long long pack2_f32(float lo, float hi) {
    unsigned long long r;
    asm("mov.b64 %0, {%1, %2};" : "=l"(r) : "r"(__float_as_uint(lo)), "r"(__float_as_uint(hi)));
    return r;
}
__device__ __forceinline__ unsigned long long fma_f32x2(unsigned long long a,
                                                        unsigned long long b,
                                                        unsigned long long c) {
    unsigned long long d;
    asm("fma.rn.f32x2 %0, %1, %2, %3;" : "=l"(d) : "l"(a), "l"(b), "l"(c));
    return d;
}
__device__ __forceinline__ float hsum_f32x2(unsigned long long v) {
    unsigned a, b;
    asm("mov.b64 {%0, %1}, %2;" : "=r"(a), "=r"(b) : "l"(v));
    return __uint_as_float(a) + __uint_as_float(b);
}

__global__ __launch_bounds__(TPB, 4)
void hashsdf_kernel(const float* __restrict__ inputs,
                    const float* __restrict__ tables,
                    const float* __restrict__ W,
                    const float* __restrict__ bias,
                    float* __restrict__ out,
                    int N, Params prm)
{
    // feature-pair-major embedding tile: sEmb2[level][point] = {feat0, feat1}
    __shared__ __align__(16) float2 sEmb2[NLVL][TILE_P];

    const int tid   = threadIdx.x;
    const int pbase = blockIdx.x * TILE_P;
    const int p     = pbase + tid;

    // ---------------- Phase 1: hash-grid encode (gather bound) ----------------
    float x = 0.f, y = 0.f, z = 0.f;
    if (p < N) {
        x = inputs[3 * p + 0];
        y = inputs[3 * p + 1];
        z = inputs[3 * p + 2];
    }

#pragma unroll
    for (int l = 0; l < NLVL; ++l) {
        const float rs = (float)prm.res[l];
        const float px = x * rs, py = y * rs, pz = z * rs;
        const float fx = floorf(px), fy = floorf(py), fz = floorf(pz);
        const float tx = px - fx, ty = py - fy, tz = pz - fz;

        const unsigned ix = (unsigned)fx, iy = (unsigned)fy, iz = (unsigned)fz;
        const unsigned hy0 = iy * PRIME_Y, hy1 = hy0 + PRIME_Y;
        const unsigned hz0 = iz * PRIME_Z, hz1 = hz0 + PRIME_Z;

        // x-pair trick: x-prime is 1 => x0/x1 corner indices are q and q^(ix^(ix+1)).
        // Even ix => XOR mask 1 => both corners live in one aligned float4.
        const unsigned xm   = ix ^ (ix + 1u);      // odd; ==1 iff ix even
        const bool     oddx = (ix & 1u) != 0u;

        const unsigned q00 = (ix ^ hy0 ^ hz0) & TMASK;
        const unsigned q01 = (ix ^ hy0 ^ hz1) & TMASK;
        const unsigned q10 = (ix ^ hy1 ^ hz0) & TMASK;
        const unsigned q11 = (ix ^ hy1 ^ hz1) & TMASK;

        const float4* __restrict__ t4 = (const float4*)tables + (size_t)l * (TBL / 2);
        const float2* __restrict__ t2 = (const float2*)tables + (size_t)l * TBL;

        // always load the float4 pair containing the x0 corner
        const float4 a00 = __ldg(t4 + (q00 >> 1));
        const float4 a01 = __ldg(t4 + (q01 >> 1));
        const float4 a10 = __ldg(t4 + (q10 >> 1));
        const float4 a11 = __ldg(t4 + (q11 >> 1));

        // x0 corner: select half of a by parity of q
        const float2 f0_00 = (q00 & 1) ? make_float2(a00.z, a00.w) : make_float2(a00.x, a00.y);
        const float2 f0_01 = (q01 & 1) ? make_float2(a01.z, a01.w) : make_float2(a01.x, a01.y);
        const float2 f0_10 = (q10 & 1) ? make_float2(a10.z, a10.w) : make_float2(a10.x, a10.y);
        const float2 f0_11 = (q11 & 1) ? make_float2(a11.z, a11.w) : make_float2(a11.x, a11.y);

        // x1 corner: other half of a (even ix), or direct float2 gather (odd ix)
        float2 f1_00 = (q00 & 1) ? make_float2(a00.x, a00.y) : make_float2(a00.z, a00.w);
        float2 f1_01 = (q01 & 1) ? make_float2(a01.x, a01.y) : make_float2(a01.z, a01.w);
        float2 f1_10 = (q10 & 1) ? make_float2(a10.x, a10.y) : make_float2(a10.z, a10.w);
        float2 f1_11 = (q11 & 1) ? make_float2(a11.x, a11.y) : make_float2(a11.z, a11.w);
        if (oddx) {
            f1_00 = __ldg(t2 + ((q00 ^ xm) & TMASK));
            f1_01 = __ldg(t2 + ((q01 ^ xm) & TMASK));
            f1_10 = __ldg(t2 + ((q10 ^ xm) & TMASK));
            f1_11 = __ldg(t2 + ((q11 ^ xm) & TMASK));
        }

        const float ux = 1.f - tx, uy = 1.f - ty, uz = 1.f - tz;
        const float a0 = ux * uy, a1 = ux * ty, a2 = tx * uy, a3 = tx * ty;
        const float w000 = a0 * uz, w001 = a0 * tz;
        const float w010 = a1 * uz, w011 = a1 * tz;
        const float w100 = a2 * uz, w101 = a2 * tz;
        const float w110 = a3 * uz, w111 = a3 * tz;

        float e0, e1;
        e0 = w000 * f0_00.x;            e1 = w000 * f0_00.y;
        e0 = fmaf(w001, f0_01.x, e0);   e1 = fmaf(w001, f0_01.y, e1);
        e0 = fmaf(w010, f0_10.x, e0);   e1 = fmaf(w010, f0_10.y, e1);
        e0 = fmaf(w011, f0_11.x, e0);   e1 = fmaf(w011, f0_11.y, e1);
        e0 = fmaf(w100, f1_00.x, e0);   e1 = fmaf(w100, f1_00.y, e1);
        e0 = fmaf(w101, f1_01.x, e0);   e1 = fmaf(w101, f1_01.y, e1);
        e0 = fmaf(w110, f1_10.x, e0);   e1 = fmaf(w110, f1_10.y, e1);
        e0 = fmaf(w111, f1_11.x, e0);   e1 = fmaf(w111, f1_11.y, e1);

        sEmb2[l][tid] = make_float2(e0, e1);   // STS.64
    }

    __syncthreads();

    // ---------------- Phase 2: [24 x 257] linear head (FMA bound) ----------------
    // 4 warps; thread owns cols c0 = wid*32+lane (0..127) and c1 = c0+128.
    // Feature pairs packed into fma.rn.f32x2; smem reads are warp-uniform
    // (broadcast => ~1 wavefront each); stores warp-contiguous.
    {
        const int wid  = tid >> 5;
        const int lane = tid & 31;
        const int c0   = wid * 32 + lane;
        const int c1   = c0 + 128;

        unsigned long long w0[NLVL], w1[NLVL];
#pragma unroll
        for (int l = 0; l < NLVL; ++l) {
            w0[l] = pack2_f32(__ldg(&W[(2 * l) * DOUT + c0]), __ldg(&W[(2 * l + 1) * DOUT + c0]));
            w1[l] = pack2_f32(__ldg(&W[(2 * l) * DOUT + c1]), __ldg(&W[(2 * l + 1) * DOUT + c1]));
        }
        const unsigned long long b0 = pack2_f32(__ldg(&bias[c0]), 0.f);
        const unsigned long long b1 = pack2_f32(__ldg(&bias[c1]), 0.f);

        for (int pg = 0; pg < TILE_P; pg += 4) {
            unsigned long long acc0[4] = {b0, b0, b0, b0};
            unsigned long long acc1[4] = {b1, b1, b1, b1};
#pragma unroll
            for (int l = 0; l < NLVL; ++l) {
                const ulonglong2 eA = *(const ulonglong2*)&sEmb2[l][pg];      // pts 0,1
                const ulonglong2 eB = *(const ulonglong2*)&sEmb2[l][pg + 2];  // pts 2,3
                acc0[0] = fma_f32x2(eA.x, w0[l], acc0[0]);
                acc1[0] = fma_f32x2(eA.x, w1[l], acc1[0]);
                acc0[1] = fma_f32x2(eA.y, w0[l], acc0[1]);
                acc1[1] = fma_f32x2(eA.y, w1[l], acc1[1]);
                acc0[2] = fma_f32x2(eB.x, w0[l], acc0[2]);
                acc1[2] = fma_f32x2(eB.x, w1[l], acc1[2]);
                acc0[3] = fma_f32x2(eB.y, w0[l], acc0[3]);
                acc1[3] = fma_f32x2(eB.y, w1[l], acc1[3]);
            }
#pragma unroll
            for (int i = 0; i < 4; ++i) {
                const size_t row = (size_t)(pbase + pg + i) * DOUT;
                __stcs(&out[row + c0], hsum_f32x2(acc0[i]));
                __stcs(&out[row + c1], hsum_f32x2(acc1[i]));
            }
        }
    }

    // ---------------- column 256 epilogue (DOUT odd) ----------------
    {
        float acc = __ldg(&bias[256]);
#pragma unroll
        for (int l = 0; l < NLVL; ++l) {
            const float2 e = sEmb2[l][tid];
            acc = fmaf(e.x, __ldg(&W[(2 * l) * DOUT + 256]), acc);
            acc = fmaf(e.y, __ldg(&W[(2 * l + 1) * DOUT + 256]), acc);
        }
        if (p < N) __stcs(&out[(size_t)p * DOUT + 256], acc);
    }
}

extern "C" void kernel_launch(void* const* d_in, const int* in_sizes, int n_in,
                              void* d_out, int out_size) {
    const float* inputs = (const float*)d_in[0];
    const float* tables = (const float*)d_in[1];
    const float* W      = (const float*)d_in[2];
    const float* bias   = (const float*)d_in[3];
    float* out          = (float*)d_out;

    const int N = in_sizes[0] / 3;

    // Replicate numpy's RES computation bit-exactly (RES[11] is analytically 2048;
    // floor outcome depends on libm rounding — do NOT hardcode).
    Params prm;
    const double growth = exp((log(2048.0) - log(16.0)) / 11.0);
    for (int l = 0; l < NLVL; ++l)
        prm.res[l] = (int)floor(16.0 * pow(growth, (double)l));

    const int grid = (N + TILE_P - 1) / TILE_P;
    hashsdf_kernel<<<grid, TPB>>>(inputs, tables, W, bias, out, N, prm);
}

// round 4
// speedup vs baseline: 1.4978x; 1.4978x over previous
#include <cuda_runtime.h>
#include <math.h>
#include <stdint.h>

// ---------------- problem constants ----------------
#define NLVL   12
#define TBL    (1u << 19)
#define TMASK  (TBL - 1u)
#define EMBD   24
#define DOUT   257
#define TPB    256            // 4 producer warps + 4 consumer warps
#define TILE_P 128            // points per tile
#define STAGES 3

#define PRIME_Y 2654435761u
#define PRIME_Z 805459861u

struct Params { int res[NLVL]; };

// ---------------- f32x2 packed helpers (sm_103a) ----------------
__device__ __forceinline__ unsigned long long pack2_f32(float lo, float hi) {
    unsigned long long r;
    asm("mov.b64 %0, {%1, %2};" : "=l"(r) : "r"(__float_as_uint(lo)), "r"(__float_as_uint(hi)));
    return r;
}
__device__ __forceinline__ unsigned long long fma_f32x2(unsigned long long a,
                                                        unsigned long long b,
                                                        unsigned long long c) {
    unsigned long long d;
    asm("fma.rn.f32x2 %0, %1, %2, %3;" : "=l"(d) : "l"(a), "l"(b), "l"(c));
    return d;
}
__device__ __forceinline__ float hsum_f32x2(unsigned long long v) {
    unsigned a, b;
    asm("mov.b64 {%0, %1}, %2;" : "=r"(a), "=r"(b) : "l"(v));
    return __uint_as_float(a) + __uint_as_float(b);
}

// ---------------- mbarrier helpers ----------------
__device__ __forceinline__ void mbar_init(unsigned long long* bar, unsigned count) {
    unsigned addr = (unsigned)__cvta_generic_to_shared(bar);
    asm volatile("mbarrier.init.shared.b64 [%0], %1;" :: "r"(addr), "r"(count) : "memory");
}
__device__ __forceinline__ void mbar_arrive(unsigned long long* bar) {
    unsigned addr = (unsigned)__cvta_generic_to_shared(bar);
    asm volatile("mbarrier.arrive.shared.b64 _, [%0];" :: "r"(addr) : "memory");
}
__device__ __forceinline__ void mbar_wait(unsigned long long* bar, unsigned parity) {
    unsigned addr = (unsigned)__cvta_generic_to_shared(bar);
    asm volatile(
        "{\n\t.reg .pred P;\n\t"
        "WAIT_%=:\n\t"
        "mbarrier.try_wait.parity.acquire.cta.shared::cta.b64 P, [%0], %1, 0x989680;\n\t"
        "@P bra.uni DONE_%=;\n\t"
        "bra.uni WAIT_%=;\n\t"
        "DONE_%=:\n\t}"
        :: "r"(addr), "r"(parity) : "memory");
}

__global__ __launch_bounds__(TPB, 2)
void hashsdf_kernel(const float* __restrict__ inputs,
                    const float* __restrict__ tables,
                    const float* __restrict__ W,
                    const float* __restrict__ bias,
                    float* __restrict__ out,
                    int N, Params prm)
{
    // ring of embedding tiles: sEmb[stage][level][point] = {feat0, feat1}
    __shared__ __align__(16) float2 sEmb[STAGES][NLVL][TILE_P];
    __shared__ __align__(8) unsigned long long barFull[STAGES], barEmpty[STAGES];

    const int tid = threadIdx.x;
    if (tid == 0) {
#pragma unroll
        for (int s = 0; s < STAGES; ++s) {
            mbar_init(&barFull[s], 128);   // 128 producer threads arrive
            mbar_init(&barEmpty[s], 128);  // 128 consumer threads arrive
        }
    }
    __syncthreads();

    const int ntiles = (N + TILE_P - 1) / TILE_P;

    if (tid < 128) {
        // ================= PRODUCER: hash-grid encode =================
        int s = 0;
        unsigned ph = 1;   // fresh barrier: parity-1 wait passes immediately
        for (int t = blockIdx.x; t < ntiles; t += gridDim.x) {
            mbar_wait(&barEmpty[s], ph);

            const int p = t * TILE_P + tid;
            float x = 0.f, y = 0.f, z = 0.f;
            if (p < N) {
                x = __ldg(&inputs[3 * p + 0]);
                y = __ldg(&inputs[3 * p + 1]);
                z = __ldg(&inputs[3 * p + 2]);
            }

#pragma unroll
            for (int l = 0; l < NLVL; ++l) {
                const float rs = (float)prm.res[l];
                const float px = x * rs, py = y * rs, pz = z * rs;
                const float fx = floorf(px), fy = floorf(py), fz = floorf(pz);
                const float tx = px - fx, ty = py - fy, tz = pz - fz;

                const unsigned ix = (unsigned)fx, iy = (unsigned)fy, iz = (unsigned)fz;
                const unsigned hy0 = iy * PRIME_Y, hy1 = hy0 + PRIME_Y;
                const unsigned hz0 = iz * PRIME_Z, hz1 = hz0 + PRIME_Z;

                // x-pair trick: x-prime is 1 => corner pair indices are q, q^(ix^(ix+1)).
                // Even ix => XOR mask 1 => both x-corners in one aligned float4.
                const unsigned xm   = ix ^ (ix + 1u);
                const bool     oddx = (ix & 1u) != 0u;

                const unsigned q00 = (ix ^ hy0 ^ hz0) & TMASK;
                const unsigned q01 = (ix ^ hy0 ^ hz1) & TMASK;
                const unsigned q10 = (ix ^ hy1 ^ hz0) & TMASK;
                const unsigned q11 = (ix ^ hy1 ^ hz1) & TMASK;

                const float4* __restrict__ t4 = (const float4*)tables + (size_t)l * (TBL / 2);

                const float4 a00 = __ldg(t4 + (q00 >> 1));
                const float4 a01 = __ldg(t4 + (q01 >> 1));
                const float4 a10 = __ldg(t4 + (q10 >> 1));
                const float4 a11 = __ldg(t4 + (q11 >> 1));

                float4 d00 = a00, d01 = a01, d10 = a10, d11 = a11;
                if (oddx) {
                    d00 = __ldg(t4 + (((q00 ^ xm) & TMASK) >> 1));
                    d01 = __ldg(t4 + (((q01 ^ xm) & TMASK) >> 1));
                    d10 = __ldg(t4 + (((q10 ^ xm) & TMASK) >> 1));
                    d11 = __ldg(t4 + (((q11 ^ xm) & TMASK) >> 1));
                }

                const float f000x = (q00 & 1) ? a00.z : a00.x, f000y = (q00 & 1) ? a00.w : a00.y;
                const float f100x = (q00 & 1) ? d00.x : d00.z, f100y = (q00 & 1) ? d00.y : d00.w;
                const float f001x = (q01 & 1) ? a01.z : a01.x, f001y = (q01 & 1) ? a01.w : a01.y;
                const float f101x = (q01 & 1) ? d01.x : d01.z, f101y = (q01 & 1) ? d01.y : d01.w;
                const float f010x = (q10 & 1) ? a10.z : a10.x, f010y = (q10 & 1) ? a10.w : a10.y;
                const float f110x = (q10 & 1) ? d10.x : d10.z, f110y = (q10 & 1) ? d10.y : d10.w;
                const float f011x = (q11 & 1) ? a11.z : a11.x, f011y = (q11 & 1) ? a11.w : a11.y;
                const float f111x = (q11 & 1) ? d11.x : d11.z, f111y = (q11 & 1) ? d11.y : d11.w;

                const float ux = 1.f - tx, uy = 1.f - ty, uz = 1.f - tz;
                const float a0 = ux * uy, a1 = ux * ty, a2 = tx * uy, a3 = tx * ty;
                const float w000 = a0 * uz, w001 = a0 * tz;
                const float w010 = a1 * uz, w011 = a1 * tz;
                const float w100 = a2 * uz, w101 = a2 * tz;
                const float w110 = a3 * uz, w111 = a3 * tz;

                float e0, e1;
                e0 = w000 * f000x;           e1 = w000 * f000y;
                e0 = fmaf(w001, f001x, e0);  e1 = fmaf(w001, f001y, e1);
                e0 = fmaf(w010, f010x, e0);  e1 = fmaf(w010, f010y, e1);
                e0 = fmaf(w011, f011x, e0);  e1 = fmaf(w011, f011y, e1);
                e0 = fmaf(w100, f100x, e0);  e1 = fmaf(w100, f100y, e1);
                e0 = fmaf(w101, f101x, e0);  e1 = fmaf(w101, f101y, e1);
                e0 = fmaf(w110, f110x, e0);  e1 = fmaf(w110, f110y, e1);
                e0 = fmaf(w111, f111x, e0);  e1 = fmaf(w111, f111y, e1);

                sEmb[s][l][tid] = make_float2(e0, e1);
            }

            mbar_arrive(&barFull[s]);
            if (++s == STAGES) { s = 0; ph ^= 1; }
        }
    } else {
        // ================= CONSUMER: [24 x 257] linear head =================
        const int ct   = tid - 128;
        const int cw   = ct >> 5;
        const int lane = ct & 31;
        const int c0   = cw * 32 + lane;       // 0..127
        const int c1   = c0 + 128;             // 128..255

        unsigned long long w0[NLVL], w1[NLVL];
        float w256[EMBD];
#pragma unroll
        for (int l = 0; l < NLVL; ++l) {
            w0[l] = pack2_f32(__ldg(&W[(2 * l) * DOUT + c0]), __ldg(&W[(2 * l + 1) * DOUT + c0]));
            w1[l] = pack2_f32(__ldg(&W[(2 * l) * DOUT + c1]), __ldg(&W[(2 * l + 1) * DOUT + c1]));
            w256[2 * l + 0] = __ldg(&W[(2 * l) * DOUT + 256]);
            w256[2 * l + 1] = __ldg(&W[(2 * l + 1) * DOUT + 256]);
        }
        const unsigned long long b0 = pack2_f32(__ldg(&bias[c0]), 0.f);
        const unsigned long long b1 = pack2_f32(__ldg(&bias[c1]), 0.f);
        const float b256 = __ldg(&bias[256]);

        int s = 0;
        unsigned ph = 0;
        for (int t = blockIdx.x; t < ntiles; t += gridDim.x) {
            mbar_wait(&barFull[s], ph);

            const int pbase = t * TILE_P;
            for (int pg = 0; pg < TILE_P; pg += 4) {
                unsigned long long acc0[4] = {b0, b0, b0, b0};
                unsigned long long acc1[4] = {b1, b1, b1, b1};
#pragma unroll
                for (int l = 0; l < NLVL; ++l) {
                    const ulonglong2 eA = *(const ulonglong2*)&sEmb[s][l][pg];      // pts 0,1
                    const ulonglong2 eB = *(const ulonglong2*)&sEmb[s][l][pg + 2];  // pts 2,3
                    acc0[0] = fma_f32x2(eA.x, w0[l], acc0[0]);
                    acc1[0] = fma_f32x2(eA.x, w1[l], acc1[0]);
                    acc0[1] = fma_f32x2(eA.y, w0[l], acc0[1]);
                    acc1[1] = fma_f32x2(eA.y, w1[l], acc1[1]);
                    acc0[2] = fma_f32x2(eB.x, w0[l], acc0[2]);
                    acc1[2] = fma_f32x2(eB.x, w1[l], acc1[2]);
                    acc0[3] = fma_f32x2(eB.y, w0[l], acc0[3]);
                    acc1[3] = fma_f32x2(eB.y, w1[l], acc1[3]);
                }
#pragma unroll
                for (int i = 0; i < 4; ++i) {
                    const int prow = pbase + pg + i;
                    if (prow < N) {
                        const size_t row = (size_t)prow * DOUT;
                        __stcs(&out[row + c0], hsum_f32x2(acc0[i]));
                        __stcs(&out[row + c1], hsum_f32x2(acc1[i]));
                    }
                }
            }

            // column 256 epilogue: consumer thread ct handles point ct of the tile
            {
                float acc = b256;
#pragma unroll
                for (int l = 0; l < NLVL; ++l) {
                    const float2 e = sEmb[s][l][ct];
                    acc = fmaf(e.x, w256[2 * l + 0], acc);
                    acc = fmaf(e.y, w256[2 * l + 1], acc);
                }
                const int prow = pbase + ct;
                if (prow < N) __stcs(&out[(size_t)prow * DOUT + 256], acc);
            }

            mbar_arrive(&barEmpty[s]);
            if (++s == STAGES) { s = 0; ph ^= 1; }
        }
    }
}

extern "C" void kernel_launch(void* const* d_in, const int* in_sizes, int n_in,
                              void* d_out, int out_size) {
    const float* inputs = (const float*)d_in[0];
    const float* tables = (const float*)d_in[1];
    const float* W      = (const float*)d_in[2];
    const float* bias   = (const float*)d_in[3];
    float* out          = (float*)d_out;

    const int N = in_sizes[0] / 3;

    // Replicate numpy's RES computation bit-exactly (RES[11] is analytically 2048;
    // floor outcome depends on libm rounding — do NOT hardcode).
    Params prm;
    const double growth = exp((log(2048.0) - log(16.0)) / 11.0);
    for (int l = 0; l < NLVL; ++l)
        prm.res[l] = (int)floor(16.0 * pow(growth, (double)l));

    int nsm = 148;
    cudaDeviceGetAttribute(&nsm, cudaDevAttrMultiProcessorCount, 0);

    const int ntiles = (N + TILE_P - 1) / TILE_P;
    int grid = 2 * nsm;                 // 2 persistent-style CTAs per SM
    if (grid > ntiles) grid = ntiles;

    hashsdf_kernel<<<grid, TPB>>>(inputs, tables, W, bias, out, N, prm);
}